// round 1
// baseline (speedup 1.0000x reference)
#include <cuda_runtime.h>

#define TSEQ 2048
#define NB   4
#define DM   1024
#define M_TOT (NB * TSEQ)   // 8192

// Scratch (device globals: allocation-free per harness rules)
__device__ float g_qkv[(size_t)NB * TSEQ * 3 * DM]; // [B,T,3C]
__device__ float g_att[(size_t)NB * TSEQ * DM];     // [B,T,C]

// ---------------------------------------------------------------------------
// SGEMM: C[M,N] = A[M,K] @ B[K,N] (+bias). 128x128 block tile, 8x8/thread,
// BK=8, 256 threads. All dims multiples of tile sizes (true for this problem).
// ---------------------------------------------------------------------------
template <int BIAS>
__global__ void __launch_bounds__(256) sgemm128(
    const float* __restrict__ A, const float* __restrict__ Bm,
    const float* __restrict__ bias, float* __restrict__ C,
    int M, int N, int K)
{
    __shared__ float As[8][128];
    __shared__ float Bs[8][128];

    const int tid = threadIdx.x;
    const int tx  = tid & 15;        // 16 col-groups of 8
    const int ty  = tid >> 4;        // 16 row-groups of 8
    const int bn  = blockIdx.x * 128;
    const int bm  = blockIdx.y * 128;

    const int arow = tid >> 1, acol = (tid & 1) << 2;
    const int brow = tid >> 5, bcol = (tid & 31) << 2;

    const float* Ap = A  + (size_t)(bm + arow) * K + acol;
    const float* Bp = Bm + (size_t)brow * N + bn + bcol;

    float acc[8][8];
#pragma unroll
    for (int i = 0; i < 8; i++)
#pragma unroll
        for (int j = 0; j < 8; j++) acc[i][j] = 0.f;

    for (int k0 = 0; k0 < K; k0 += 8) {
        float4 av = *(const float4*)(Ap + k0);
        float4 bv = *(const float4*)(Bp + (size_t)k0 * N);
        __syncthreads();
        As[acol + 0][arow] = av.x;
        As[acol + 1][arow] = av.y;
        As[acol + 2][arow] = av.z;
        As[acol + 3][arow] = av.w;
        *(float4*)&Bs[brow][bcol] = bv;
        __syncthreads();
#pragma unroll
        for (int kk = 0; kk < 8; kk++) {
            float a[8], b[8];
            *(float4*)&a[0] = *(const float4*)&As[kk][ty * 8];
            *(float4*)&a[4] = *(const float4*)&As[kk][ty * 8 + 4];
            *(float4*)&b[0] = *(const float4*)&Bs[kk][tx * 8];
            *(float4*)&b[4] = *(const float4*)&Bs[kk][tx * 8 + 4];
#pragma unroll
            for (int i = 0; i < 8; i++)
#pragma unroll
                for (int j = 0; j < 8; j++)
                    acc[i][j] += a[i] * b[j];
        }
    }

    float bb[8] = {0.f, 0.f, 0.f, 0.f, 0.f, 0.f, 0.f, 0.f};
    if (BIAS) {
        *(float4*)&bb[0] = *(const float4*)(bias + bn + tx * 8);
        *(float4*)&bb[4] = *(const float4*)(bias + bn + tx * 8 + 4);
    }
    float* Cp = C + (size_t)(bm + ty * 8) * N + bn + tx * 8;
#pragma unroll
    for (int i = 0; i < 8; i++) {
        float4 c0, c1;
        c0.x = acc[i][0] + bb[0]; c0.y = acc[i][1] + bb[1];
        c0.z = acc[i][2] + bb[2]; c0.w = acc[i][3] + bb[3];
        c1.x = acc[i][4] + bb[4]; c1.y = acc[i][5] + bb[5];
        c1.z = acc[i][6] + bb[6]; c1.w = acc[i][7] + bb[7];
        *(float4*)(Cp + (size_t)i * N)     = c0;
        *(float4*)(Cp + (size_t)i * N + 4) = c1;
    }
}

// ---------------------------------------------------------------------------
// Flash attention (causal, fp32). One block = one (b, h, q-tile of 128 rows).
// 256 threads: tx (0..15) covers 64 head dims / S cols in groups of 4,
//              ty (0..15) covers 128 rows in groups of 8.
// Per KV tile (64 keys): S = Q@K^T (regs), online softmax (shfl over the
// 16-lane tx group), P staged in padded smem, O += P@V (regs).
// K is stored in smem d-major with a 16B-chunk XOR swizzle so the S-GEMM
// LDS128 reads are conflict-free.
// ---------------------------------------------------------------------------
__global__ void __launch_bounds__(256) attn_kernel(
    const float* __restrict__ qkv, float* __restrict__ out)
{
    extern __shared__ float sm[];
    float* Qs = sm;                  // [64 d][128 rows]
    float* Ks = Qs + 64 * 128;       // [64 d][64 keys], swizzled 16B chunks
    float* Vs = Ks + 64 * 64;        // [64 keys][64 d]
    float* Ps = Vs + 64 * 64;        // [128 rows][stride 68]

    const int tid = threadIdx.x;
    const int tx  = tid & 15;
    const int ty  = tid >> 4;
    const int q0  = blockIdx.x * 128;
    const int b   = blockIdx.y >> 4;
    const int h   = blockIdx.y & 15;

    const float* base = qkv + (size_t)b * TSEQ * (3 * DM) + h * 64;

    // Load Q tile, transposed to d-major
    for (int i = tid; i < 2048; i += 256) {           // 2048 float4s
        int row = i >> 4;
        int d0  = (i & 15) << 2;
        float4 v = *(const float4*)(base + (size_t)(q0 + row) * (3 * DM) + d0);
        Qs[(d0 + 0) * 128 + row] = v.x;
        Qs[(d0 + 1) * 128 + row] = v.y;
        Qs[(d0 + 2) * 128 + row] = v.z;
        Qs[(d0 + 3) * 128 + row] = v.w;
    }

    float o[8][4];
    float m[8], l[8];
#pragma unroll
    for (int i = 0; i < 8; i++) {
        m[i] = -1e30f;
        l[i] = 0.f;
#pragma unroll
        for (int j = 0; j < 4; j++) o[i][j] = 0.f;
    }

    const int jmax = (q0 + 127) >> 6;   // inclusive: causal tile bound
    for (int j = 0; j <= jmax; j++) {
        const int k0 = j << 6;
        __syncthreads();   // protect Ks/Vs/Ps from previous iteration's readers
        // Load K (swizzled, d-major) and V (natural) tiles
        for (int i = tid; i < 1024; i += 256) {       // 1024 float4s
            int key = i >> 4;
            int d0  = (i & 15) << 2;
            const float* kp = base + DM + (size_t)(k0 + key) * (3 * DM) + d0;
            float4 kv = *(const float4*)kp;
            float4 vv = *(const float4*)(kp + DM);
            int chunk = key >> 2, kr = key & 3;
            Ks[(d0 + 0) * 64 + ((chunk ^ ((d0 + 0) & 15)) << 2) + kr] = kv.x;
            Ks[(d0 + 1) * 64 + ((chunk ^ ((d0 + 1) & 15)) << 2) + kr] = kv.y;
            Ks[(d0 + 2) * 64 + ((chunk ^ ((d0 + 2) & 15)) << 2) + kr] = kv.z;
            Ks[(d0 + 3) * 64 + ((chunk ^ ((d0 + 3) & 15)) << 2) + kr] = kv.w;
            *(float4*)&Vs[key * 64 + d0] = vv;
        }
        __syncthreads();

        // S = Q @ K^T  (rows ty*8..+7, cols tx*4..+3)
        float s[8][4];
#pragma unroll
        for (int i = 0; i < 8; i++)
#pragma unroll
            for (int jj = 0; jj < 4; jj++) s[i][jj] = 0.f;

#pragma unroll 16
        for (int kk = 0; kk < 64; kk++) {
            float q8[8];
            *(float4*)&q8[0] = *(const float4*)&Qs[kk * 128 + ty * 8];
            *(float4*)&q8[4] = *(const float4*)&Qs[kk * 128 + ty * 8 + 4];
            float4 kv = *(const float4*)&Ks[kk * 64 + ((tx ^ (kk & 15)) << 2)];
            float k4[4] = {kv.x, kv.y, kv.z, kv.w};
#pragma unroll
            for (int i = 0; i < 8; i++)
#pragma unroll
                for (int jj = 0; jj < 4; jj++)
                    s[i][jj] += q8[i] * k4[jj];
        }

        // Online softmax over this tile
        const bool domask = (k0 + 63 > q0);
#pragma unroll
        for (int i = 0; i < 8; i++) {
            const int qg = q0 + ty * 8 + i;
            float sv[4];
#pragma unroll
            for (int jj = 0; jj < 4; jj++) {
                float v = s[i][jj] * 0.125f;   // 1/sqrt(64)
                if (domask && (k0 + tx * 4 + jj > qg)) v = -1e30f;
                sv[jj] = v;
            }
            float r = fmaxf(fmaxf(sv[0], sv[1]), fmaxf(sv[2], sv[3]));
            r = fmaxf(r, __shfl_xor_sync(0xffffffffu, r, 1));
            r = fmaxf(r, __shfl_xor_sync(0xffffffffu, r, 2));
            r = fmaxf(r, __shfl_xor_sync(0xffffffffu, r, 4));
            r = fmaxf(r, __shfl_xor_sync(0xffffffffu, r, 8));
            float mn = fmaxf(m[i], r);
            float sc = __expf(m[i] - mn);
            float rs = 0.f;
#pragma unroll
            for (int jj = 0; jj < 4; jj++) {
                float p = __expf(sv[jj] - mn);
                rs += p;
                Ps[(ty * 8 + i) * 68 + tx * 4 + jj] = p;
            }
            rs += __shfl_xor_sync(0xffffffffu, rs, 1);
            rs += __shfl_xor_sync(0xffffffffu, rs, 2);
            rs += __shfl_xor_sync(0xffffffffu, rs, 4);
            rs += __shfl_xor_sync(0xffffffffu, rs, 8);
            l[i] = l[i] * sc + rs;
            m[i] = mn;
#pragma unroll
            for (int jj = 0; jj < 4; jj++) o[i][jj] *= sc;
        }
        __syncthreads();

        // O += P @ V
#pragma unroll 8
        for (int c = 0; c < 64; c++) {
            float4 vv = *(const float4*)&Vs[c * 64 + tx * 4];
#pragma unroll
            for (int i = 0; i < 8; i++) {
                float p = Ps[(ty * 8 + i) * 68 + c];
                o[i][0] += p * vv.x;
                o[i][1] += p * vv.y;
                o[i][2] += p * vv.z;
                o[i][3] += p * vv.w;
            }
        }
    }

    // Normalize and write out[b, t, h*64 + d] ([B,T,C] layout)
    float* op = out + ((size_t)b * TSEQ + q0 + ty * 8) * DM + h * 64 + tx * 4;
#pragma unroll
    for (int i = 0; i < 8; i++) {
        float inv = 1.f / l[i];
        float4 r;
        r.x = o[i][0] * inv;
        r.y = o[i][1] * inv;
        r.z = o[i][2] * inv;
        r.w = o[i][3] * inv;
        *(float4*)(op + (size_t)i * DM) = r;
    }
}

// ---------------------------------------------------------------------------
extern "C" void kernel_launch(void* const* d_in, const int* in_sizes, int n_in,
                              void* d_out, int out_size)
{
    const float* x      = (const float*)d_in[0];
    const float* w_qkv  = (const float*)d_in[1];
    const float* w_proj = (const float*)d_in[2];
    const float* b_proj = (const float*)d_in[3];
    float* out = (float*)d_out;

    float* qkv; cudaGetSymbolAddress((void**)&qkv, g_qkv);
    float* att; cudaGetSymbolAddress((void**)&att, g_att);

    const int SMEM = (64 * 128 + 64 * 64 + 64 * 64 + 128 * 68) * 4;  // 100352 B
    cudaFuncSetAttribute(attn_kernel,
                         cudaFuncAttributeMaxDynamicSharedMemorySize, SMEM);

    // 1) QKV = x @ w_qkv   (8192 x 3072 x 1024)
    sgemm128<0><<<dim3(3 * DM / 128, M_TOT / 128), 256>>>(
        x, w_qkv, nullptr, qkv, M_TOT, 3 * DM, DM);

    // 2) causal MHA -> att [B,T,C]
    attn_kernel<<<dim3(TSEQ / 128, NB * 16), 256, SMEM>>>(qkv, att);

    // 3) out = att @ w_proj + b_proj   (8192 x 1024 x 1024)
    sgemm128<1><<<dim3(DM / 128, M_TOT / 128), 256>>>(
        att, w_proj, b_proj, out, M_TOT, DM, DM);
}

// round 2
// speedup vs baseline: 1.6023x; 1.6023x over previous
#include <cuda_runtime.h>
#include <cstdint>

#define TSEQ 2048
#define NB   4
#define DM   1024
#define M_TOT (NB * TSEQ)   // 8192

// Scratch (device globals: allocation-free per harness rules)
__device__ float g_qkv[(size_t)NB * TSEQ * 3 * DM]; // [B,T,3C]
__device__ float g_att[(size_t)NB * TSEQ * DM];     // [B,T,C]

__device__ __forceinline__ float cvt_tf32(float x) {
    uint32_t u;
    asm("cvt.rna.tf32.f32 %0, %1;" : "=r"(u) : "f"(x));
    return __uint_as_float(u);
}

__device__ __forceinline__ void mma_tf32(
    float& c0, float& c1, float& c2, float& c3,
    uint32_t a0, uint32_t a1, uint32_t a2, uint32_t a3,
    uint32_t b0, uint32_t b1)
{
    asm volatile(
        "mma.sync.aligned.m16n8k8.row.col.f32.tf32.tf32.f32 "
        "{%0,%1,%2,%3}, {%4,%5,%6,%7}, {%8,%9}, {%0,%1,%2,%3};"
        : "+f"(c0), "+f"(c1), "+f"(c2), "+f"(c3)
        : "r"(a0), "r"(a1), "r"(a2), "r"(a3), "r"(b0), "r"(b1));
}

// ---------------------------------------------------------------------------
// TF32 tensor-core GEMM: C[M,N] = A[M,K] @ B[K,N] (+bias)
// CTA tile 128x128, BK=32, 256 threads (8 warps, 2x4 warp grid, 64x32/warp).
// A smem padded to stride 36, B to 132 -> conflict-free fragment LDS.
// Register-prefetch double buffering over the 32-wide K slabs.
// ---------------------------------------------------------------------------
template <int BIAS>
__global__ void __launch_bounds__(256) gemm_tf32(
    const float* __restrict__ A, const float* __restrict__ Bm,
    const float* __restrict__ bias, float* __restrict__ C,
    int M, int N, int K)
{
    __shared__ float As[128 * 36];   // [row][k] stride 36
    __shared__ float Bs[32 * 132];   // [k][n]   stride 132

    const int tid  = threadIdx.x;
    const int lane = tid & 31;
    const int wid  = tid >> 5;
    const int wm   = (wid & 1) * 64;      // warp m offset
    const int wn   = (wid >> 1) * 32;     // warp n offset
    const int bm   = blockIdx.y * 128;
    const int bn   = blockIdx.x * 128;

    // global load mapping (4 float4 each for A and B per thread)
    const int ar[4] = { (tid + 0*256) >> 3, (tid + 1*256) >> 3,
                        (tid + 2*256) >> 3, (tid + 3*256) >> 3 };
    const int ac    = (tid & 7) << 2;
    const int br[4] = { (tid + 0*256) >> 5, (tid + 1*256) >> 5,
                        (tid + 2*256) >> 5, (tid + 3*256) >> 5 };
    const int bc    = (tid & 31) << 2;

    const float* Ag = A  + (size_t)bm * K;
    const float* Bg = Bm + bn;

    float acc[4][4][4];   // [mi][ni][c]
#pragma unroll
    for (int mi = 0; mi < 4; mi++)
#pragma unroll
        for (int ni = 0; ni < 4; ni++)
#pragma unroll
            for (int c = 0; c < 4; c++) acc[mi][ni][c] = 0.f;

    float4 pa[4], pb[4];
    // preload first slab
#pragma unroll
    for (int t = 0; t < 4; t++) {
        pa[t] = *(const float4*)(Ag + (size_t)ar[t] * K + ac);
        pb[t] = *(const float4*)(Bg + (size_t)br[t] * N + bc);
    }

    for (int k0 = 0; k0 < K; k0 += 32) {
        // store current slab (with tf32 rounding)
#pragma unroll
        for (int t = 0; t < 4; t++) {
            float* ap = &As[ar[t] * 36 + ac];
            ap[0] = cvt_tf32(pa[t].x); ap[1] = cvt_tf32(pa[t].y);
            ap[2] = cvt_tf32(pa[t].z); ap[3] = cvt_tf32(pa[t].w);
            float* bp = &Bs[br[t] * 132 + bc];
            bp[0] = cvt_tf32(pb[t].x); bp[1] = cvt_tf32(pb[t].y);
            bp[2] = cvt_tf32(pb[t].z); bp[3] = cvt_tf32(pb[t].w);
        }
        __syncthreads();

        // prefetch next slab
        if (k0 + 32 < K) {
#pragma unroll
            for (int t = 0; t < 4; t++) {
                pa[t] = *(const float4*)(Ag + (size_t)ar[t] * K + k0 + 32 + ac);
                pb[t] = *(const float4*)(Bg + (size_t)(k0 + 32 + br[t]) * N + bc);
            }
        }

        // compute 4 k-steps of 8
#pragma unroll
        for (int kk = 0; kk < 4; kk++) {
            const int kb = kk * 8;
            uint32_t af[4][4], bf[4][2];
#pragma unroll
            for (int mi = 0; mi < 4; mi++) {
                const int r = wm + mi * 16 + (lane >> 2);
                const int k = kb + (lane & 3);
                af[mi][0] = __float_as_uint(As[r * 36 + k]);
                af[mi][1] = __float_as_uint(As[(r + 8) * 36 + k]);
                af[mi][2] = __float_as_uint(As[r * 36 + k + 4]);
                af[mi][3] = __float_as_uint(As[(r + 8) * 36 + k + 4]);
            }
#pragma unroll
            for (int ni = 0; ni < 4; ni++) {
                const int n = wn + ni * 8 + (lane >> 2);
                const int k = kb + (lane & 3);
                bf[ni][0] = __float_as_uint(Bs[k * 132 + n]);
                bf[ni][1] = __float_as_uint(Bs[(k + 4) * 132 + n]);
            }
#pragma unroll
            for (int mi = 0; mi < 4; mi++)
#pragma unroll
                for (int ni = 0; ni < 4; ni++)
                    mma_tf32(acc[mi][ni][0], acc[mi][ni][1],
                             acc[mi][ni][2], acc[mi][ni][3],
                             af[mi][0], af[mi][1], af[mi][2], af[mi][3],
                             bf[ni][0], bf[ni][1]);
        }
        __syncthreads();
    }

    // epilogue: D fragment c0,c1 at (row, 2c..2c+1), c2,c3 at (row+8, ...)
#pragma unroll
    for (int mi = 0; mi < 4; mi++) {
        const int r0 = bm + wm + mi * 16 + (lane >> 2);
#pragma unroll
        for (int ni = 0; ni < 4; ni++) {
            const int cc = bn + wn + ni * 8 + (lane & 3) * 2;
            float b0 = 0.f, b1 = 0.f;
            if (BIAS) { b0 = bias[cc]; b1 = bias[cc + 1]; }
            C[(size_t)r0 * N + cc]           = acc[mi][ni][0] + b0;
            C[(size_t)r0 * N + cc + 1]       = acc[mi][ni][1] + b1;
            C[(size_t)(r0 + 8) * N + cc]     = acc[mi][ni][2] + b0;
            C[(size_t)(r0 + 8) * N + cc + 1] = acc[mi][ni][3] + b1;
        }
    }
}

// ---------------------------------------------------------------------------
// Flash attention (causal, fp32) — unchanged from R0 baseline.
// ---------------------------------------------------------------------------
__global__ void __launch_bounds__(256) attn_kernel(
    const float* __restrict__ qkv, float* __restrict__ out)
{
    extern __shared__ float sm[];
    float* Qs = sm;                  // [64 d][128 rows]
    float* Ks = Qs + 64 * 128;       // [64 d][64 keys], swizzled 16B chunks
    float* Vs = Ks + 64 * 64;        // [64 keys][64 d]
    float* Ps = Vs + 64 * 64;        // [128 rows][stride 68]

    const int tid = threadIdx.x;
    const int tx  = tid & 15;
    const int ty  = tid >> 4;
    const int q0  = blockIdx.x * 128;
    const int b   = blockIdx.y >> 4;
    const int h   = blockIdx.y & 15;

    const float* base = qkv + (size_t)b * TSEQ * (3 * DM) + h * 64;

    for (int i = tid; i < 2048; i += 256) {
        int row = i >> 4;
        int d0  = (i & 15) << 2;
        float4 v = *(const float4*)(base + (size_t)(q0 + row) * (3 * DM) + d0);
        Qs[(d0 + 0) * 128 + row] = v.x;
        Qs[(d0 + 1) * 128 + row] = v.y;
        Qs[(d0 + 2) * 128 + row] = v.z;
        Qs[(d0 + 3) * 128 + row] = v.w;
    }

    float o[8][4];
    float m[8], l[8];
#pragma unroll
    for (int i = 0; i < 8; i++) {
        m[i] = -1e30f;
        l[i] = 0.f;
#pragma unroll
        for (int j = 0; j < 4; j++) o[i][j] = 0.f;
    }

    const int jmax = (q0 + 127) >> 6;
    for (int j = 0; j <= jmax; j++) {
        const int k0 = j << 6;
        __syncthreads();
        for (int i = tid; i < 1024; i += 256) {
            int key = i >> 4;
            int d0  = (i & 15) << 2;
            const float* kp = base + DM + (size_t)(k0 + key) * (3 * DM) + d0;
            float4 kv = *(const float4*)kp;
            float4 vv = *(const float4*)(kp + DM);
            int chunk = key >> 2, kr = key & 3;
            Ks[(d0 + 0) * 64 + ((chunk ^ ((d0 + 0) & 15)) << 2) + kr] = kv.x;
            Ks[(d0 + 1) * 64 + ((chunk ^ ((d0 + 1) & 15)) << 2) + kr] = kv.y;
            Ks[(d0 + 2) * 64 + ((chunk ^ ((d0 + 2) & 15)) << 2) + kr] = kv.z;
            Ks[(d0 + 3) * 64 + ((chunk ^ ((d0 + 3) & 15)) << 2) + kr] = kv.w;
            *(float4*)&Vs[key * 64 + d0] = vv;
        }
        __syncthreads();

        float s[8][4];
#pragma unroll
        for (int i = 0; i < 8; i++)
#pragma unroll
            for (int jj = 0; jj < 4; jj++) s[i][jj] = 0.f;

#pragma unroll 16
        for (int kk = 0; kk < 64; kk++) {
            float q8[8];
            *(float4*)&q8[0] = *(const float4*)&Qs[kk * 128 + ty * 8];
            *(float4*)&q8[4] = *(const float4*)&Qs[kk * 128 + ty * 8 + 4];
            float4 kv = *(const float4*)&Ks[kk * 64 + ((tx ^ (kk & 15)) << 2)];
            float k4[4] = {kv.x, kv.y, kv.z, kv.w};
#pragma unroll
            for (int i = 0; i < 8; i++)
#pragma unroll
                for (int jj = 0; jj < 4; jj++)
                    s[i][jj] += q8[i] * k4[jj];
        }

        const bool domask = (k0 + 63 > q0);
#pragma unroll
        for (int i = 0; i < 8; i++) {
            const int qg = q0 + ty * 8 + i;
            float sv[4];
#pragma unroll
            for (int jj = 0; jj < 4; jj++) {
                float v = s[i][jj] * 0.125f;
                if (domask && (k0 + tx * 4 + jj > qg)) v = -1e30f;
                sv[jj] = v;
            }
            float r = fmaxf(fmaxf(sv[0], sv[1]), fmaxf(sv[2], sv[3]));
            r = fmaxf(r, __shfl_xor_sync(0xffffffffu, r, 1));
            r = fmaxf(r, __shfl_xor_sync(0xffffffffu, r, 2));
            r = fmaxf(r, __shfl_xor_sync(0xffffffffu, r, 4));
            r = fmaxf(r, __shfl_xor_sync(0xffffffffu, r, 8));
            float mn = fmaxf(m[i], r);
            float sc = __expf(m[i] - mn);
            float rs = 0.f;
#pragma unroll
            for (int jj = 0; jj < 4; jj++) {
                float p = __expf(sv[jj] - mn);
                rs += p;
                Ps[(ty * 8 + i) * 68 + tx * 4 + jj] = p;
            }
            rs += __shfl_xor_sync(0xffffffffu, rs, 1);
            rs += __shfl_xor_sync(0xffffffffu, rs, 2);
            rs += __shfl_xor_sync(0xffffffffu, rs, 4);
            rs += __shfl_xor_sync(0xffffffffu, rs, 8);
            l[i] = l[i] * sc + rs;
            m[i] = mn;
#pragma unroll
            for (int jj = 0; jj < 4; jj++) o[i][jj] *= sc;
        }
        __syncthreads();

#pragma unroll 8
        for (int c = 0; c < 64; c++) {
            float4 vv = *(const float4*)&Vs[c * 64 + tx * 4];
#pragma unroll
            for (int i = 0; i < 8; i++) {
                float p = Ps[(ty * 8 + i) * 68 + c];
                o[i][0] += p * vv.x;
                o[i][1] += p * vv.y;
                o[i][2] += p * vv.z;
                o[i][3] += p * vv.w;
            }
        }
    }

    float* op = out + ((size_t)b * TSEQ + q0 + ty * 8) * DM + h * 64 + tx * 4;
#pragma unroll
    for (int i = 0; i < 8; i++) {
        float inv = 1.f / l[i];
        float4 r;
        r.x = o[i][0] * inv;
        r.y = o[i][1] * inv;
        r.z = o[i][2] * inv;
        r.w = o[i][3] * inv;
        *(float4*)(op + (size_t)i * DM) = r;
    }
}

// ---------------------------------------------------------------------------
extern "C" void kernel_launch(void* const* d_in, const int* in_sizes, int n_in,
                              void* d_out, int out_size)
{
    const float* x      = (const float*)d_in[0];
    const float* w_qkv  = (const float*)d_in[1];
    const float* w_proj = (const float*)d_in[2];
    const float* b_proj = (const float*)d_in[3];
    float* out = (float*)d_out;

    float* qkv; cudaGetSymbolAddress((void**)&qkv, g_qkv);
    float* att; cudaGetSymbolAddress((void**)&att, g_att);

    const int SMEM = (64 * 128 + 64 * 64 + 64 * 64 + 128 * 68) * 4;  // 100352 B
    cudaFuncSetAttribute(attn_kernel,
                         cudaFuncAttributeMaxDynamicSharedMemorySize, SMEM);

    // 1) QKV = x @ w_qkv   (8192 x 3072 x 1024), TF32 tensor cores
    gemm_tf32<0><<<dim3(3 * DM / 128, M_TOT / 128), 256>>>(
        x, w_qkv, nullptr, qkv, M_TOT, 3 * DM, DM);

    // 2) causal MHA -> att [B,T,C]
    attn_kernel<<<dim3(TSEQ / 128, NB * 16), 256, SMEM>>>(qkv, att);

    // 3) out = att @ w_proj + b_proj   (8192 x 1024 x 1024), TF32 tensor cores
    gemm_tf32<1><<<dim3(DM / 128, M_TOT / 128), 256>>>(
        att, w_proj, b_proj, out, M_TOT, DM, DM);
}

// round 3
// speedup vs baseline: 2.4392x; 1.5223x over previous
#include <cuda_runtime.h>
#include <cstdint>

#define TSEQ 2048
#define NB   4
#define DM   1024
#define M_TOT (NB * TSEQ)   // 8192

// Scratch (device globals: allocation-free per harness rules)
__device__ float g_qkv[(size_t)NB * TSEQ * 3 * DM]; // [B,T,3C]
__device__ float g_att[(size_t)NB * TSEQ * DM];     // [B,T,C]

__device__ __forceinline__ float cvt_tf32(float x) {
    uint32_t u;
    asm("cvt.rna.tf32.f32 %0, %1;" : "=r"(u) : "f"(x));
    return __uint_as_float(u);
}

__device__ __forceinline__ void mma_tf32(
    float& c0, float& c1, float& c2, float& c3,
    uint32_t a0, uint32_t a1, uint32_t a2, uint32_t a3,
    uint32_t b0, uint32_t b1)
{
    asm volatile(
        "mma.sync.aligned.m16n8k8.row.col.f32.tf32.tf32.f32 "
        "{%0,%1,%2,%3}, {%4,%5,%6,%7}, {%8,%9}, {%0,%1,%2,%3};"
        : "+f"(c0), "+f"(c1), "+f"(c2), "+f"(c3)
        : "r"(a0), "r"(a1), "r"(a2), "r"(a3), "r"(b0), "r"(b1));
}

// ---------------------------------------------------------------------------
// TF32 tensor-core GEMM: C[M,N] = A[M,K] @ B[K,N] (+bias)  (unchanged from R1)
// ---------------------------------------------------------------------------
template <int BIAS>
__global__ void __launch_bounds__(256) gemm_tf32(
    const float* __restrict__ A, const float* __restrict__ Bm,
    const float* __restrict__ bias, float* __restrict__ C,
    int M, int N, int K)
{
    __shared__ float As[128 * 36];   // [row][k] stride 36
    __shared__ float Bs[32 * 132];   // [k][n]   stride 132

    const int tid  = threadIdx.x;
    const int lane = tid & 31;
    const int wid  = tid >> 5;
    const int wm   = (wid & 1) * 64;
    const int wn   = (wid >> 1) * 32;
    const int bm   = blockIdx.y * 128;
    const int bn   = blockIdx.x * 128;

    const int ar[4] = { (tid + 0*256) >> 3, (tid + 1*256) >> 3,
                        (tid + 2*256) >> 3, (tid + 3*256) >> 3 };
    const int ac    = (tid & 7) << 2;
    const int br[4] = { (tid + 0*256) >> 5, (tid + 1*256) >> 5,
                        (tid + 2*256) >> 5, (tid + 3*256) >> 5 };
    const int bc    = (tid & 31) << 2;

    const float* Ag = A  + (size_t)bm * K;
    const float* Bg = Bm + bn;

    float acc[4][4][4];
#pragma unroll
    for (int mi = 0; mi < 4; mi++)
#pragma unroll
        for (int ni = 0; ni < 4; ni++)
#pragma unroll
            for (int c = 0; c < 4; c++) acc[mi][ni][c] = 0.f;

    float4 pa[4], pb[4];
#pragma unroll
    for (int t = 0; t < 4; t++) {
        pa[t] = *(const float4*)(Ag + (size_t)ar[t] * K + ac);
        pb[t] = *(const float4*)(Bg + (size_t)br[t] * N + bc);
    }

    for (int k0 = 0; k0 < K; k0 += 32) {
#pragma unroll
        for (int t = 0; t < 4; t++) {
            float* ap = &As[ar[t] * 36 + ac];
            ap[0] = cvt_tf32(pa[t].x); ap[1] = cvt_tf32(pa[t].y);
            ap[2] = cvt_tf32(pa[t].z); ap[3] = cvt_tf32(pa[t].w);
            float* bp = &Bs[br[t] * 132 + bc];
            bp[0] = cvt_tf32(pb[t].x); bp[1] = cvt_tf32(pb[t].y);
            bp[2] = cvt_tf32(pb[t].z); bp[3] = cvt_tf32(pb[t].w);
        }
        __syncthreads();

        if (k0 + 32 < K) {
#pragma unroll
            for (int t = 0; t < 4; t++) {
                pa[t] = *(const float4*)(Ag + (size_t)ar[t] * K + k0 + 32 + ac);
                pb[t] = *(const float4*)(Bg + (size_t)(k0 + 32 + br[t]) * N + bc);
            }
        }

#pragma unroll
        for (int kk = 0; kk < 4; kk++) {
            const int kb = kk * 8;
            uint32_t af[4][4], bf[4][2];
#pragma unroll
            for (int mi = 0; mi < 4; mi++) {
                const int r = wm + mi * 16 + (lane >> 2);
                const int k = kb + (lane & 3);
                af[mi][0] = __float_as_uint(As[r * 36 + k]);
                af[mi][1] = __float_as_uint(As[(r + 8) * 36 + k]);
                af[mi][2] = __float_as_uint(As[r * 36 + k + 4]);
                af[mi][3] = __float_as_uint(As[(r + 8) * 36 + k + 4]);
            }
#pragma unroll
            for (int ni = 0; ni < 4; ni++) {
                const int n = wn + ni * 8 + (lane >> 2);
                const int k = kb + (lane & 3);
                bf[ni][0] = __float_as_uint(Bs[k * 132 + n]);
                bf[ni][1] = __float_as_uint(Bs[(k + 4) * 132 + n]);
            }
#pragma unroll
            for (int mi = 0; mi < 4; mi++)
#pragma unroll
                for (int ni = 0; ni < 4; ni++)
                    mma_tf32(acc[mi][ni][0], acc[mi][ni][1],
                             acc[mi][ni][2], acc[mi][ni][3],
                             af[mi][0], af[mi][1], af[mi][2], af[mi][3],
                             bf[ni][0], bf[ni][1]);
        }
        __syncthreads();
    }

#pragma unroll
    for (int mi = 0; mi < 4; mi++) {
        const int r0 = bm + wm + mi * 16 + (lane >> 2);
#pragma unroll
        for (int ni = 0; ni < 4; ni++) {
            const int cc = bn + wn + ni * 8 + (lane & 3) * 2;
            float b0 = 0.f, b1 = 0.f;
            if (BIAS) { b0 = bias[cc]; b1 = bias[cc + 1]; }
            C[(size_t)r0 * N + cc]           = acc[mi][ni][0] + b0;
            C[(size_t)r0 * N + cc + 1]       = acc[mi][ni][1] + b1;
            C[(size_t)(r0 + 8) * N + cc]     = acc[mi][ni][2] + b0;
            C[(size_t)(r0 + 8) * N + cc + 1] = acc[mi][ni][3] + b1;
        }
    }
}

// ---------------------------------------------------------------------------
// Flash attention (causal), TF32 tensor cores.
// CTA = (b, h, 128-row q-tile). 8 warps, warp w owns rows w*16..w*16+15.
// KV tile BC=64. All smem row-major stride 68 (conflict-free fragment LDS).
// Softmax scale pre-folded into Q. Online softmax in C-fragment layout;
// P staged via smem per-warp (only __syncwarp between softmax and PV).
// ---------------------------------------------------------------------------
#define QSTR 68

__global__ void __launch_bounds__(256) attn_mma(
    const float* __restrict__ qkv, float* __restrict__ out)
{
    extern __shared__ float sm[];
    float* Qs = sm;                    // [128][68]
    float* Ks = Qs + 128 * QSTR;       // [64][68]
    float* Vs = Ks + 64 * QSTR;        // [64][68]
    float* Ps = Vs + 64 * QSTR;        // [128][68]

    const int tid  = threadIdx.x;
    const int lane = tid & 31;
    const int wid  = tid >> 5;
    const int wm   = wid * 16;
    const int qr   = lane >> 2;   // 0..7
    const int qc   = lane & 3;    // 0..3
    const int q0   = blockIdx.x * 128;
    const int b    = blockIdx.y >> 4;
    const int h    = blockIdx.y & 15;

    const float* base = qkv + (size_t)b * TSEQ * (3 * DM) + h * 64;

    // Load Q tile (pre-scaled by 1/sqrt(hd), tf32-rounded)
    for (int i = tid; i < 128 * 16; i += 256) {
        int row = i >> 4, d0 = (i & 15) << 2;
        float4 v = *(const float4*)(base + (size_t)(q0 + row) * (3 * DM) + d0);
        float4 w;
        w.x = cvt_tf32(v.x * 0.125f); w.y = cvt_tf32(v.y * 0.125f);
        w.z = cvt_tf32(v.z * 0.125f); w.w = cvt_tf32(v.w * 0.125f);
        *(float4*)&Qs[row * QSTR + d0] = w;
    }

    float oacc[8][4];
#pragma unroll
    for (int ni = 0; ni < 8; ni++)
#pragma unroll
        for (int c = 0; c < 4; c++) oacc[ni][c] = 0.f;
    float m0 = -1e30f, m1 = -1e30f, l0 = 0.f, l1 = 0.f;

    const int r0g = q0 + wm + qr;
    const int r1g = r0g + 8;
    const int ntiles = (q0 >> 6) + 2;

    for (int j = 0; j < ntiles; j++) {
        const int k0 = j << 6;
        __syncthreads();
        // Load K,V tile (row-major, tf32)
        for (int i = tid; i < 64 * 16; i += 256) {
            int key = i >> 4, d0 = (i & 15) << 2;
            const float* kp = base + DM + (size_t)(k0 + key) * (3 * DM) + d0;
            float4 kv = *(const float4*)kp;
            float4 vv = *(const float4*)(kp + DM);
            float4 kw, vw;
            kw.x = cvt_tf32(kv.x); kw.y = cvt_tf32(kv.y);
            kw.z = cvt_tf32(kv.z); kw.w = cvt_tf32(kv.w);
            vw.x = cvt_tf32(vv.x); vw.y = cvt_tf32(vv.y);
            vw.z = cvt_tf32(vv.z); vw.w = cvt_tf32(vv.w);
            *(float4*)&Ks[key * QSTR + d0] = kw;
            *(float4*)&Vs[key * QSTR + d0] = vw;
        }
        __syncthreads();

        // ---- S = Q @ K^T (scaled) ----
        float sacc[8][4];
#pragma unroll
        for (int ni = 0; ni < 8; ni++)
#pragma unroll
            for (int c = 0; c < 4; c++) sacc[ni][c] = 0.f;

#pragma unroll
        for (int kb = 0; kb < 64; kb += 8) {
            uint32_t a0 = __float_as_uint(Qs[(wm + qr) * QSTR + kb + qc]);
            uint32_t a1 = __float_as_uint(Qs[(wm + qr + 8) * QSTR + kb + qc]);
            uint32_t a2 = __float_as_uint(Qs[(wm + qr) * QSTR + kb + qc + 4]);
            uint32_t a3 = __float_as_uint(Qs[(wm + qr + 8) * QSTR + kb + qc + 4]);
#pragma unroll
            for (int ni = 0; ni < 8; ni++) {
                uint32_t b0 = __float_as_uint(Ks[(ni * 8 + qr) * QSTR + kb + qc]);
                uint32_t b1 = __float_as_uint(Ks[(ni * 8 + qr) * QSTR + kb + qc + 4]);
                mma_tf32(sacc[ni][0], sacc[ni][1], sacc[ni][2], sacc[ni][3],
                         a0, a1, a2, a3, b0, b1);
            }
        }

        // ---- online softmax (C-fragment layout) ----
        const bool domask = (k0 + 63 > q0 + wm);
        float mx0 = -1e30f, mx1 = -1e30f;
#pragma unroll
        for (int ni = 0; ni < 8; ni++) {
            if (domask) {
                const int cb = k0 + ni * 8 + qc * 2;
                if (cb     > r0g) sacc[ni][0] = -1e30f;
                if (cb + 1 > r0g) sacc[ni][1] = -1e30f;
                if (cb     > r1g) sacc[ni][2] = -1e30f;
                if (cb + 1 > r1g) sacc[ni][3] = -1e30f;
            }
            mx0 = fmaxf(mx0, fmaxf(sacc[ni][0], sacc[ni][1]));
            mx1 = fmaxf(mx1, fmaxf(sacc[ni][2], sacc[ni][3]));
        }
        mx0 = fmaxf(mx0, __shfl_xor_sync(0xffffffffu, mx0, 1));
        mx0 = fmaxf(mx0, __shfl_xor_sync(0xffffffffu, mx0, 2));
        mx1 = fmaxf(mx1, __shfl_xor_sync(0xffffffffu, mx1, 1));
        mx1 = fmaxf(mx1, __shfl_xor_sync(0xffffffffu, mx1, 2));

        const float mn0 = fmaxf(m0, mx0), mn1 = fmaxf(m1, mx1);
        const float sc0 = __expf(m0 - mn0), sc1 = __expf(m1 - mn1);
        float rs0 = 0.f, rs1 = 0.f;
#pragma unroll
        for (int ni = 0; ni < 8; ni++) {
            float p0 = __expf(sacc[ni][0] - mn0);
            float p1 = __expf(sacc[ni][1] - mn0);
            float p2 = __expf(sacc[ni][2] - mn1);
            float p3 = __expf(sacc[ni][3] - mn1);
            rs0 += p0 + p1; rs1 += p2 + p3;
            float2 t0; t0.x = cvt_tf32(p0); t0.y = cvt_tf32(p1);
            float2 t1; t1.x = cvt_tf32(p2); t1.y = cvt_tf32(p3);
            *(float2*)&Ps[(wm + qr) * QSTR + ni * 8 + qc * 2]     = t0;
            *(float2*)&Ps[(wm + qr + 8) * QSTR + ni * 8 + qc * 2] = t1;
            oacc[ni][0] *= sc0; oacc[ni][1] *= sc0;
            oacc[ni][2] *= sc1; oacc[ni][3] *= sc1;
        }
        rs0 += __shfl_xor_sync(0xffffffffu, rs0, 1);
        rs0 += __shfl_xor_sync(0xffffffffu, rs0, 2);
        rs1 += __shfl_xor_sync(0xffffffffu, rs1, 1);
        rs1 += __shfl_xor_sync(0xffffffffu, rs1, 2);
        l0 = l0 * sc0 + rs0; l1 = l1 * sc1 + rs1;
        m0 = mn0; m1 = mn1;
        __syncwarp();

        // ---- O += P @ V ----
#pragma unroll
        for (int kb = 0; kb < 64; kb += 8) {
            uint32_t a0 = __float_as_uint(Ps[(wm + qr) * QSTR + kb + qc]);
            uint32_t a1 = __float_as_uint(Ps[(wm + qr + 8) * QSTR + kb + qc]);
            uint32_t a2 = __float_as_uint(Ps[(wm + qr) * QSTR + kb + qc + 4]);
            uint32_t a3 = __float_as_uint(Ps[(wm + qr + 8) * QSTR + kb + qc + 4]);
#pragma unroll
            for (int ni = 0; ni < 8; ni++) {
                uint32_t b0 = __float_as_uint(Vs[(kb + qc) * QSTR + ni * 8 + qr]);
                uint32_t b1 = __float_as_uint(Vs[(kb + qc + 4) * QSTR + ni * 8 + qr]);
                mma_tf32(oacc[ni][0], oacc[ni][1], oacc[ni][2], oacc[ni][3],
                         a0, a1, a2, a3, b0, b1);
            }
        }
    }

    // Normalize + write out[b, t, h*64 + d]
    const float inv0 = 1.f / l0, inv1 = 1.f / l1;
    float* o0 = out + ((size_t)b * TSEQ + r0g) * DM + h * 64;
    float* o1 = out + ((size_t)b * TSEQ + r1g) * DM + h * 64;
#pragma unroll
    for (int ni = 0; ni < 8; ni++) {
        const int cc = ni * 8 + qc * 2;
        float2 t0; t0.x = oacc[ni][0] * inv0; t0.y = oacc[ni][1] * inv0;
        float2 t1; t1.x = oacc[ni][2] * inv1; t1.y = oacc[ni][3] * inv1;
        *(float2*)(o0 + cc) = t0;
        *(float2*)(o1 + cc) = t1;
    }
}

// ---------------------------------------------------------------------------
extern "C" void kernel_launch(void* const* d_in, const int* in_sizes, int n_in,
                              void* d_out, int out_size)
{
    const float* x      = (const float*)d_in[0];
    const float* w_qkv  = (const float*)d_in[1];
    const float* w_proj = (const float*)d_in[2];
    const float* b_proj = (const float*)d_in[3];
    float* out = (float*)d_out;

    float* qkv; cudaGetSymbolAddress((void**)&qkv, g_qkv);
    float* att; cudaGetSymbolAddress((void**)&att, g_att);

    const int SMEM = (128 + 64 + 64 + 128) * QSTR * 4;   // 104448 B
    cudaFuncSetAttribute(attn_mma,
                         cudaFuncAttributeMaxDynamicSharedMemorySize, SMEM);

    // 1) QKV = x @ w_qkv   (8192 x 3072 x 1024)
    gemm_tf32<0><<<dim3(3 * DM / 128, M_TOT / 128), 256>>>(
        x, w_qkv, nullptr, qkv, M_TOT, 3 * DM, DM);

    // 2) causal MHA -> att [B,T,C], TF32 tensor cores
    attn_mma<<<dim3(TSEQ / 128, NB * 16), 256, SMEM>>>(qkv, att);

    // 3) out = att @ w_proj + b_proj   (8192 x 1024 x 1024)
    gemm_tf32<1><<<dim3(DM / 128, M_TOT / 128), 256>>>(
        att, w_proj, b_proj, out, M_TOT, DM, DM);
}